// round 3
// baseline (speedup 1.0000x reference)
#include <cuda_runtime.h>
#include <cstdint>

// LookupAlignConvolution2d: 3x3 VALID conv, NHWC, |w| < 0.01 masked to 0.
// x: (32, 64, 64, 256) f32 -> d_in[0]
// w: (256, 256, 3, 3)  f32 -> d_in[1]  (OIHW)
// b: (256,)            f32 -> d_in[2]
// out: (32, 62, 62, 256) f32
//
// Implicit GEMM: M = 123008, N = 256, K = 2304 (9 taps x 256 c).
// R2: fp32 FFMA2 (fma.rn.f32x2) GEMM, double-buffered smem, conflict-free STS.

#define SPARSE_TH 0.01f

#define NB    32
#define HIN   64
#define WIN   64
#define CIN   256
#define COUT  256
#define HOUT  62
#define WOUT  62

#define BM 128
#define BN 64
#define BK 16
#define ASTRIDE 130      // 4*ASTRIDE mod 32banks => seg offsets {0,8,16,24}: conflict-free STS
#define CHUNKS 144       // 9 taps * (256/BK)

// Masked + transposed weights: W_t[tap][c][ko], tap = dy*3+dx. 9*256*256 floats.
__device__ float g_wt[9 * CIN * COUT];

// ---------------------------------------------------------------------------
__global__ void prep_weights_kernel(const float* __restrict__ w) {
    int idx = blockIdx.x * blockDim.x + threadIdx.x;   // < 9*256*256 exactly
    int ko   = idx & 255;
    int rest = idx >> 8;
    int c    = rest & 255;
    int tap  = rest >> 8;          // 0..8
    float v = w[ko * (CIN * 9) + c * 9 + tap];
    if (fabsf(v) < SPARSE_TH) v = 0.0f;
    g_wt[idx] = v;
}

// ---------------------------------------------------------------------------
__device__ __forceinline__ unsigned smem_addr_u32(const void* p) {
    return (unsigned)__cvta_generic_to_shared(p);
}
__device__ __forceinline__ unsigned long long lds_b64(unsigned addr) {
    unsigned long long v;
    asm("ld.shared.b64 %0, [%1];" : "=l"(v) : "r"(addr));
    return v;
}
__device__ __forceinline__ unsigned long long bcast_f32x2(float f) {
    unsigned long long v;
    unsigned u = __float_as_uint(f);
    asm("mov.b64 %0, {%1, %1};" : "=l"(v) : "r"(u));
    return v;
}
__device__ __forceinline__ unsigned long long ffma2(unsigned long long a,
                                                    unsigned long long b,
                                                    unsigned long long c) {
    unsigned long long d;
    asm("fma.rn.f32x2 %0, %1, %2, %3;" : "=l"(d) : "l"(a), "l"(b), "l"(c));
    return d;
}
__device__ __forceinline__ float2 unpack_f32x2(unsigned long long v) {
    float2 r;
    unsigned lo, hi;
    asm("mov.b64 {%0, %1}, %2;" : "=r"(lo), "=r"(hi) : "l"(v));
    r.x = __uint_as_float(lo);
    r.y = __uint_as_float(hi);
    return r;
}

// ---------------------------------------------------------------------------
// Grid: (4 n-tiles, 961 m-tiles) — n fastest so the 4 blocks sharing an
// x-tile are launch-adjacent (L2 reuse of A). Block: 256 threads (16x16).
// Each thread: 8 rows x 4 cols held as 16 f32x2 accumulators (row pairs).
// ---------------------------------------------------------------------------
__global__ __launch_bounds__(256) void conv_sgemm_kernel(
    const float* __restrict__ x,
    const float* __restrict__ bias,
    float* __restrict__ out)
{
    __shared__ float As[2][BK * ASTRIDE];   // A^T: As[buf][k][m]
    __shared__ float Bs[2][BK * BN];        // Bs[buf][k][n]

    const int tid   = threadIdx.x;
    const int ntile = blockIdx.x;        // 0..3
    const int mtile = blockIdx.y;        // 0..960
    const int tx    = tid & 15;
    const int ty    = tid >> 4;

    // ---- A-load assignment: rows ra and ra+64, 16B segment seg ----
    const int ra   = tid >> 2;           // 0..63
    const int seg  = tid & 3;            // 0..3
    const int seg4 = seg << 2;
    int base0, base1;
    {
        int m = mtile * BM + ra;
        int n = m / (HOUT * WOUT);
        int r = m - n * (HOUT * WOUT);
        int y = r / WOUT;
        int xx = r - y * WOUT;
        base0 = ((n * HIN + y) * WIN + xx) * CIN;
        m += 64;
        n = m / (HOUT * WOUT);
        r = m - n * (HOUT * WOUT);
        y = r / WOUT;
        xx = r - y * WOUT;
        base1 = ((n * HIN + y) * WIN + xx) * CIN;
    }

    // ---- B-load assignment ----
    const int bk   = tid >> 4;           // 0..15 (k row in Bs)
    const int bn4  = (tid & 15) << 2;    // 0..60
    const int ncol = ntile * BN + bn4;

    // ---- accumulators ----
    unsigned long long acc[4][4];
#pragma unroll
    for (int i = 0; i < 4; i++)
#pragma unroll
        for (int j = 0; j < 4; j++) acc[i][j] = 0ULL;

    const unsigned as_base = smem_addr_u32(&As[0][0]) + (unsigned)(ty * 8) * 4u;
    const unsigned bs_base = smem_addr_u32(&Bs[0][0]);

    // ---- staged global loads ----
    float4 av0, av1, bv;
#define PREFETCH(KK) {                                                        \
        int tap_ = (KK) >> 4;                                                 \
        int c0_  = ((KK) & 15) << 4;                                          \
        int dy_  = tap_ / 3;                                                  \
        int dx_  = tap_ - dy_ * 3;                                            \
        int toff_ = (dy_ * WIN + dx_) * CIN + c0_;                            \
        av0 = *(const float4*)(x + base0 + toff_ + seg4);                     \
        av1 = *(const float4*)(x + base1 + toff_ + seg4);                     \
        bv  = *(const float4*)(g_wt + tap_ * (CIN * COUT)                     \
                               + (c0_ + bk) * COUT + ncol);                   \
    }

    PREFETCH(0);
    int p = 0;

#pragma unroll 1
    for (int kk = 0; kk < CHUNKS; kk++) {
        // ---- commit staged chunk into buffer p ----
        float* Asp = As[p];
        float* Bsp = Bs[p];
        const int k0 = seg4;
        Asp[(k0 + 0) * ASTRIDE + ra] = av0.x;
        Asp[(k0 + 1) * ASTRIDE + ra] = av0.y;
        Asp[(k0 + 2) * ASTRIDE + ra] = av0.z;
        Asp[(k0 + 3) * ASTRIDE + ra] = av0.w;
        Asp[(k0 + 0) * ASTRIDE + ra + 64] = av1.x;
        Asp[(k0 + 1) * ASTRIDE + ra + 64] = av1.y;
        Asp[(k0 + 2) * ASTRIDE + ra + 64] = av1.z;
        Asp[(k0 + 3) * ASTRIDE + ra + 64] = av1.w;
        *(float4*)(&Bsp[bk * BN + bn4]) = bv;

        __syncthreads();

        // ---- prefetch next chunk (lands during compute below) ----
        if (kk + 1 < CHUNKS) PREFETCH(kk + 1);

        // ---- compute on buffer p ----
        const unsigned abuf = as_base + (unsigned)p * (BK * ASTRIDE * 4);
        const float* brow = Bsp + (tx << 2);
#pragma unroll
        for (int k = 0; k < BK; k++) {
            const unsigned aaddr = abuf + (unsigned)(k * ASTRIDE) * 4u;
            unsigned long long a01 = lds_b64(aaddr);
            unsigned long long a23 = lds_b64(aaddr + 8);
            unsigned long long a45 = lds_b64(aaddr + 16);
            unsigned long long a67 = lds_b64(aaddr + 24);

            float4 bf = *(const float4*)(brow + k * BN);
            unsigned long long b0 = bcast_f32x2(bf.x);
            unsigned long long b1 = bcast_f32x2(bf.y);
            unsigned long long b2 = bcast_f32x2(bf.z);
            unsigned long long b3 = bcast_f32x2(bf.w);

            acc[0][0] = ffma2(a01, b0, acc[0][0]);
            acc[0][1] = ffma2(a01, b1, acc[0][1]);
            acc[0][2] = ffma2(a01, b2, acc[0][2]);
            acc[0][3] = ffma2(a01, b3, acc[0][3]);
            acc[1][0] = ffma2(a23, b0, acc[1][0]);
            acc[1][1] = ffma2(a23, b1, acc[1][1]);
            acc[1][2] = ffma2(a23, b2, acc[1][2]);
            acc[1][3] = ffma2(a23, b3, acc[1][3]);
            acc[2][0] = ffma2(a45, b0, acc[2][0]);
            acc[2][1] = ffma2(a45, b1, acc[2][1]);
            acc[2][2] = ffma2(a45, b2, acc[2][2]);
            acc[2][3] = ffma2(a45, b3, acc[2][3]);
            acc[3][0] = ffma2(a67, b0, acc[3][0]);
            acc[3][1] = ffma2(a67, b1, acc[3][1]);
            acc[3][2] = ffma2(a67, b2, acc[3][2]);
            acc[3][3] = ffma2(a67, b3, acc[3][3]);
        }
        p ^= 1;
    }
#undef PREFETCH

    // ---- epilogue: + bias ----
    const int colbase = ncol - bn4 + (tx << 2);   // ntile*BN + tx*4
    const float4 bb = *(const float4*)(bias + colbase);
    const int mrow0 = mtile * BM + ty * 8;

#pragma unroll
    for (int ip = 0; ip < 4; ip++) {
        float2 c0 = unpack_f32x2(acc[ip][0]);
        float2 c1 = unpack_f32x2(acc[ip][1]);
        float2 c2 = unpack_f32x2(acc[ip][2]);
        float2 c3 = unpack_f32x2(acc[ip][3]);
        const long m = mrow0 + 2 * ip;

        float4 o;
        o.x = c0.x + bb.x; o.y = c1.x + bb.y; o.z = c2.x + bb.z; o.w = c3.x + bb.w;
        *(float4*)(out + m * COUT + colbase) = o;
        o.x = c0.y + bb.x; o.y = c1.y + bb.y; o.z = c2.y + bb.z; o.w = c3.y + bb.w;
        *(float4*)(out + (m + 1) * COUT + colbase) = o;
    }
}

// ---------------------------------------------------------------------------
extern "C" void kernel_launch(void* const* d_in, const int* in_sizes, int n_in,
                              void* d_out, int out_size) {
    const float* x    = (const float*)d_in[0];
    const float* w    = (const float*)d_in[1];
    const float* bias = (const float*)d_in[2];
    float* out        = (float*)d_out;

    prep_weights_kernel<<<(9 * CIN * COUT) / 256, 256>>>(w);

    dim3 grid(COUT / BN, (NB * HOUT * WOUT) / BM);   // (4, 961)
    conv_sgemm_kernel<<<grid, 256>>>(x, bias, out);
}

// round 15
// speedup vs baseline: 1.7236x; 1.7236x over previous
#include <cuda_runtime.h>
#include <cuda_bf16.h>
#include <cstdint>

// LookupAlignConvolution2d: 3x3 VALID conv, NHWC, |w| < 0.01 masked to 0.
// x: (32,64,64,256) f32, w: (256,256,3,3) f32 OIHW, b: (256,) f32
// out: (32,62,62,256) f32
//
// R15 (audited resubmit; R10-R14 never ran: broker timeouts): baseline-PTX
// tensor cores (mma.sync.m16n8k16 bf16 — compute_103 has no tcgen05).
// Split precision:
//   x = xh + xl, w = wh + wl;  D += xh*wh + xh*wl + xl*wh   (drop xl*wl ~2^-18)
// Implicit GEMM: M = 123008 (961x128), N = 256 (2 tiles of 128), K = 2304.

#define SPARSE_TH 0.01f
#define NB    32
#define HIN   64
#define WIN   64
#define CIN   256
#define COUT  256
#define HOUT  62
#define WOUT  62

#define BM 128
#define BN 128
#define BK 32
#define CHUNKS 72            // 2304 / 32; 8 chunks per tap

// smem layout (bytes, per stage):
//   AXF: raw x f32 chunk, 128 rows x 144B (32 f32 + 16B pad)   = 18432
//   AH/AL: bf16 tiles, 128 rows x 80B (64B data + 16B pad)     = 10240 each
//   BH/BL: bf16 tiles, 32 rows x 256B, XOR-16B-chunk swizzle   =  8192 each
#define AXF_OFF 0
#define AH_OFF  18432
#define AL_OFF  28672
#define BH_OFF  38912
#define BL_OFF  47104
#define STAGE   55296
#define SMEM_TOTAL (2 * STAGE)     // 110592

// Pre-split masked weights, layout [tap][c][ko] (= GEMM B row-major [k][n]).
__device__ __nv_bfloat16 g_wbh[9 * CIN * COUT];
__device__ __nv_bfloat16 g_wbl[9 * CIN * COUT];

// ---------------------------------------------------------------------------
__global__ void prep_weights_kernel(const float* __restrict__ w) {
    int idx = blockIdx.x * blockDim.x + threadIdx.x;   // < 9*256*256
    int ko  = idx & 255;
    int c   = (idx >> 8) & 255;
    int tap = idx >> 16;
    float v = w[ko * (CIN * 9) + c * 9 + tap];
    if (fabsf(v) < SPARSE_TH) v = 0.0f;
    __nv_bfloat16 h = __float2bfloat16_rn(v);
    __nv_bfloat16 l = __float2bfloat16_rn(v - __bfloat162float(h));
    g_wbh[idx] = h;            // idx == tap*65536 + c*256 + ko
    g_wbl[idx] = l;
}

// ---------------------------------------------------------------------------
__device__ __forceinline__ unsigned smem_u32(const void* p) {
    return (unsigned)__cvta_generic_to_shared(p);
}
__device__ __forceinline__ void cp16(unsigned dst, const void* src) {
    asm volatile("cp.async.ca.shared.global [%0], [%1], 16;"
                 :: "r"(dst), "l"(src));
}
__device__ __forceinline__ void cp_commit() {
    asm volatile("cp.async.commit_group;" ::: "memory");
}
__device__ __forceinline__ void cp_wait0() {
    asm volatile("cp.async.wait_group 0;" ::: "memory");
}
__device__ __forceinline__ void ldsm_x4(unsigned addr, unsigned& r0, unsigned& r1,
                                        unsigned& r2, unsigned& r3) {
    asm volatile("ldmatrix.sync.aligned.m8n8.x4.shared.b16 {%0,%1,%2,%3}, [%4];"
                 : "=r"(r0), "=r"(r1), "=r"(r2), "=r"(r3) : "r"(addr));
}
__device__ __forceinline__ void ldsm_x4_t(unsigned addr, unsigned& r0, unsigned& r1,
                                          unsigned& r2, unsigned& r3) {
    asm volatile("ldmatrix.sync.aligned.m8n8.x4.trans.shared.b16 {%0,%1,%2,%3}, [%4];"
                 : "=r"(r0), "=r"(r1), "=r"(r2), "=r"(r3) : "r"(addr));
}
__device__ __forceinline__ void mma16816(float* d, const unsigned* a,
                                         unsigned b0, unsigned b1) {
    asm volatile(
        "mma.sync.aligned.m16n8k16.row.col.f32.bf16.bf16.f32 "
        "{%0,%1,%2,%3}, {%4,%5,%6,%7}, {%8,%9}, {%0,%1,%2,%3};"
        : "+f"(d[0]), "+f"(d[1]), "+f"(d[2]), "+f"(d[3])
        : "r"(a[0]), "r"(a[1]), "r"(a[2]), "r"(a[3]), "r"(b0), "r"(b1));
}
__device__ __forceinline__ unsigned b2u(__nv_bfloat162 v) {
    return *reinterpret_cast<unsigned*>(&v);
}
__device__ __forceinline__ void cvt8(float4 a, float4 b, uint4& hi, uint4& lo) {
    __nv_bfloat162 h0 = __float22bfloat162_rn(make_float2(a.x, a.y));
    __nv_bfloat162 h1 = __float22bfloat162_rn(make_float2(a.z, a.w));
    __nv_bfloat162 h2 = __float22bfloat162_rn(make_float2(b.x, b.y));
    __nv_bfloat162 h3 = __float22bfloat162_rn(make_float2(b.z, b.w));
    float2 g0 = __bfloat1622float2(h0);
    float2 g1 = __bfloat1622float2(h1);
    float2 g2 = __bfloat1622float2(h2);
    float2 g3 = __bfloat1622float2(h3);
    __nv_bfloat162 l0 = __float22bfloat162_rn(make_float2(a.x - g0.x, a.y - g0.y));
    __nv_bfloat162 l1 = __float22bfloat162_rn(make_float2(a.z - g1.x, a.w - g1.y));
    __nv_bfloat162 l2 = __float22bfloat162_rn(make_float2(b.x - g2.x, b.y - g2.y));
    __nv_bfloat162 l3 = __float22bfloat162_rn(make_float2(b.z - g3.x, b.w - g3.y));
    hi = make_uint4(b2u(h0), b2u(h1), b2u(h2), b2u(h3));
    lo = make_uint4(b2u(l0), b2u(l1), b2u(l2), b2u(l3));
}

// ---------------------------------------------------------------------------
// Grid (961, 2). 256 threads = 8 warps, 2(m) x 4(n); warp tile 64x32.
__global__ __launch_bounds__(256, 2) void conv_mma_kernel(
    const float* __restrict__ x,
    const float* __restrict__ bias,
    float* __restrict__ out)
{
    extern __shared__ char smem[];
    const unsigned sb = smem_u32(smem);
    const int tid   = threadIdx.x;
    const int lane  = tid & 31;
    const int wid   = tid >> 5;
    const int wm    = wid >> 2;          // 0..1
    const int wn    = wid & 3;           // 0..3
    const int mtile = blockIdx.x;        // 0..960
    const int ntile = blockIdx.y;        // 0..1

    // ---- loader assignment ----
    const int ar  = tid >> 1;            // A row 0..127
    const int as  = tid & 1;             // 16-float segment
    int abase;
    {
        int m = mtile * BM + ar;
        int n = m / (HOUT * WOUT);
        int r = m - n * (HOUT * WOUT);
        int y = r / WOUT;
        int xx = r - y * WOUT;
        abase = ((n * HIN + y) * WIN + xx) * CIN;
    }
    const int bc   = tid >> 3;           // B k-row 0..31
    const int bs   = tid & 7;            // 32B segment
    const int bsrc_off = ntile * 128 + bs * 16;   // elems within ko row

    // cp.async destination addresses (stage-relative)
    const unsigned axf_dst = sb + AXF_OFF + ar * 144 + as * 64;
    const unsigned bh_dst0 = sb + BH_OFF + bc * 256 + ((bs * 32 +  0) ^ ((bc & 7) << 4));
    const unsigned bh_dst1 = sb + BH_OFF + bc * 256 + ((bs * 32 + 16) ^ ((bc & 7) << 4));
    const unsigned bl_dst0 = bh_dst0 + (BL_OFF - BH_OFF);
    const unsigned bl_dst1 = bh_dst1 + (BL_OFF - BH_OFF);

#define ISSUE(KK, PBUF) {                                                     \
        const int tap_ = (KK) >> 3;                                           \
        const int c0_  = ((KK) & 7) << 5;                                     \
        const int dy_ = tap_ / 3, dx_ = tap_ - dy_ * 3;                       \
        const int toff_ = (dy_ * WIN + dx_) * CIN + c0_;                      \
        const unsigned so_ = (PBUF) * STAGE;                                  \
        const float* asrc_ = x + abase + toff_ + as * 16;                     \
        cp16(axf_dst + so_ +  0, asrc_ +  0);                                 \
        cp16(axf_dst + so_ + 16, asrc_ +  4);                                 \
        cp16(axf_dst + so_ + 32, asrc_ +  8);                                 \
        cp16(axf_dst + so_ + 48, asrc_ + 12);                                 \
        const __nv_bfloat16* bh_ = g_wbh + tap_ * 65536 + (c0_ + bc) * 256 + bsrc_off; \
        const __nv_bfloat16* bl_ = g_wbl + tap_ * 65536 + (c0_ + bc) * 256 + bsrc_off; \
        cp16(bh_dst0 + so_, bh_);                                             \
        cp16(bh_dst1 + so_, bh_ + 8);                                         \
        cp16(bl_dst0 + so_, bl_);                                             \
        cp16(bl_dst1 + so_, bl_ + 8);                                         \
        cp_commit();                                                          \
    }

    // ---- accumulators: acc[i][jn][4]  (i: 4 m-frags, jn: 4 n8 blocks) ----
    float acc[4][4][4];
#pragma unroll
    for (int i = 0; i < 4; i++)
#pragma unroll
        for (int j = 0; j < 4; j++)
#pragma unroll
            for (int q = 0; q < 4; q++) acc[i][j][q] = 0.0f;

    // fragment smem addresses (stage-relative)
    const unsigned a_rowsel = (unsigned)((wm * 64 + (lane & 15)) * 80 + (lane >> 4) * 16);
    const int b_k = lane & 15;                       // k row within 16
    const unsigned b_nb = (unsigned)(wn * 64 + (lane >> 4) * 16);  // byte col base

    ISSUE(0, 0);

#pragma unroll 1
    for (int kk = 0; kk < CHUNKS; kk++) {
        const int p = kk & 1;
        const unsigned so = p * STAGE;

        cp_wait0();
        __syncthreads();

        // ---- convert: x f32 -> Ah/Al bf16 tiles ----
        {
            const unsigned src = sb + AXF_OFF + so + ar * 144 + as * 64;
            float4 v0 = *(const float4*)(smem + (src - sb) +  0);
            float4 v1 = *(const float4*)(smem + (src - sb) + 16);
            float4 v2 = *(const float4*)(smem + (src - sb) + 32);
            float4 v3 = *(const float4*)(smem + (src - sb) + 48);
            uint4 h0, l0, h1, l1;
            cvt8(v0, v1, h0, l0);
            cvt8(v2, v3, h1, l1);
            char* dsth = smem + AH_OFF + so + ar * 80 + as * 32;
            char* dstl = smem + AL_OFF + so + ar * 80 + as * 32;
            *(uint4*)(dsth)      = h0;
            *(uint4*)(dsth + 16) = h1;
            *(uint4*)(dstl)      = l0;
            *(uint4*)(dstl + 16) = l1;
        }
        __syncthreads();

        if (kk + 1 < CHUNKS) ISSUE(kk + 1, p ^ 1);

        // ---- compute: 3 variants x 2 k-steps x 16 mma ----
#pragma unroll
        for (int v = 0; v < 3; v++) {
            const unsigned pa = sb + so + ((v == 2) ? AL_OFF : AH_OFF);
            const unsigned pb = sb + so + ((v == 1) ? BL_OFF : BH_OFF);
#pragma unroll
            for (int s = 0; s < 2; s++) {
                unsigned a[4][4];
#pragma unroll
                for (int i = 0; i < 4; i++) {
                    unsigned addr = pa + a_rowsel + (unsigned)(i * 16 * 80) + (unsigned)(s * 32);
                    ldsm_x4(addr, a[i][0], a[i][1], a[i][2], a[i][3]);
                }
                unsigned b[8];
#pragma unroll
                for (int j = 0; j < 2; j++) {
                    const int krow = s * 16 + b_k;
                    unsigned nbyte = (b_nb + (unsigned)(j * 32)) ^ ((unsigned)(krow & 7) << 4);
                    unsigned addr = pb + (unsigned)krow * 256 + nbyte;
                    ldsm_x4_t(addr, b[j*4+0], b[j*4+1], b[j*4+2], b[j*4+3]);
                }
#pragma unroll
                for (int i = 0; i < 4; i++) {
#pragma unroll
                    for (int jn = 0; jn < 4; jn++)
                        mma16816(acc[i][jn], a[i], b[jn*2], b[jn*2+1]);
                }
            }
        }
    }
#undef ISSUE

    // ---- epilogue: registers -> out, + bias ----
    const int colbase = ntile * BN + wn * 32;
    const int rowbase = mtile * BM + wm * 64;
#pragma unroll
    for (int jn = 0; jn < 4; jn++) {
        const int col = colbase + jn * 8 + (lane & 3) * 2;
        const float2 bb = *(const float2*)(bias + col);
#pragma unroll
        for (int i = 0; i < 4; i++) {
            const int m0 = rowbase + i * 16 + (lane >> 2);
            float2 o0, o1;
            o0.x = acc[i][jn][0] + bb.x;  o0.y = acc[i][jn][1] + bb.y;
            o1.x = acc[i][jn][2] + bb.x;  o1.y = acc[i][jn][3] + bb.y;
            *(float2*)(out + (long)m0 * COUT + col)        = o0;
            *(float2*)(out + (long)(m0 + 8) * COUT + col)  = o1;
        }
    }
}

// ---------------------------------------------------------------------------
extern "C" void kernel_launch(void* const* d_in, const int* in_sizes, int n_in,
                              void* d_out, int out_size) {
    const float* x    = (const float*)d_in[0];
    const float* w    = (const float*)d_in[1];
    const float* bias = (const float*)d_in[2];
    float* out        = (float*)d_out;

    cudaFuncSetAttribute(conv_mma_kernel,
                         cudaFuncAttributeMaxDynamicSharedMemorySize, SMEM_TOTAL);

    prep_weights_kernel<<<(9 * CIN * COUT) / 256, 256>>>(w);

    dim3 grid(961, 2);
    conv_mma_kernel<<<grid, 256, SMEM_TOTAL>>>(x, bias, out);
}